// round 2
// baseline (speedup 1.0000x reference)
#include <cuda_runtime.h>
#include <cstdint>

#define SEQ   4096
#define EMB   512
#define HH    512      // per-direction hidden
#define G4    2048     // 4*HH
#define TAGS  8
#define START_TAG 6
#define STOP_TAG  7
#define NEGV  (-10000.0f)

// ---------------- scratch (device globals; no runtime alloc) ----------------
__device__ float g_emb[SEQ * EMB];              // 8 MB
__device__ float g_xproj[2][SEQ][G4];           // 64 MB
__device__ float g_h[2][SEQ][HH];               // 16 MB
__device__ float g_feats[SEQ * TAGS];
__device__ int   g_flags[64];

// ---------------- init: zero the step flags each launch ----------------
__global__ void init_kernel() {
    if (threadIdx.x < 64) g_flags[threadIdx.x] = 0;
}

// ---------------- embedding gather ----------------
__global__ void embed_kernel(const int* __restrict__ sentence,
                             const float* __restrict__ wembed) {
    int t = blockIdx.x;
    int tok = sentence[t];
    const float4* src = (const float4*)(wembed + (size_t)tok * EMB);
    float4* dst = (float4*)(g_emb + (size_t)t * EMB);
    dst[threadIdx.x] = src[threadIdx.x];   // 128 threads * 4 floats = 512
}

// ---------------- x-projection SGEMM: C[m][n] = emb[m,:] . W[n,:] + b[n] ----
#define BM 128
#define BN 64
#define BKK 16
__global__ void gemm_kernel(const float* __restrict__ w_f, const float* __restrict__ b_f,
                            const float* __restrict__ w_b, const float* __restrict__ b_b) {
    __shared__ float As[BKK][BM];
    __shared__ float Bs[BKK][BN];
    const float* W    = blockIdx.z ? w_b : w_f;
    const float* bias = blockIdx.z ? b_b : b_f;
    int m0 = blockIdx.y * BM;
    int n0 = blockIdx.x * BN;
    int tid = threadIdx.x;
    int tx = tid & 15;       // 0..15 -> N
    int ty = tid >> 4;       // 0..15 -> M

    float acc[8][4];
#pragma unroll
    for (int i = 0; i < 8; i++)
#pragma unroll
        for (int j = 0; j < 4; j++) acc[i][j] = 0.f;

    for (int kt = 0; kt < EMB; kt += BKK) {
        // load A tile (emb): 128 rows x 16 k  -> transposed into As[k][m]
#pragma unroll
        for (int i = 0; i < 2; i++) {
            int f = tid * 2 + i;           // 0..511
            int m = f >> 2;
            int kq = (f & 3) * 4;
            float4 v = *(const float4*)(g_emb + (size_t)(m0 + m) * EMB + kt + kq);
            As[kq + 0][m] = v.x; As[kq + 1][m] = v.y;
            As[kq + 2][m] = v.z; As[kq + 3][m] = v.w;
        }
        {   // load B tile (W): 64 rows x 16 k -> Bs[k][n]
            int f = tid;                   // 0..255
            int n = f >> 2;
            int kq = (f & 3) * 4;
            float4 v = *(const float4*)(W + (size_t)(n0 + n) * EMB + kt + kq);
            Bs[kq + 0][n] = v.x; Bs[kq + 1][n] = v.y;
            Bs[kq + 2][n] = v.z; Bs[kq + 3][n] = v.w;
        }
        __syncthreads();
#pragma unroll
        for (int k = 0; k < BKK; k++) {
            float4 a0 = *(const float4*)&As[k][ty * 8];
            float4 a1 = *(const float4*)&As[k][ty * 8 + 4];
            float4 bv = *(const float4*)&Bs[k][tx * 4];
            float a[8] = {a0.x, a0.y, a0.z, a0.w, a1.x, a1.y, a1.z, a1.w};
            float b[4] = {bv.x, bv.y, bv.z, bv.w};
#pragma unroll
            for (int i = 0; i < 8; i++)
#pragma unroll
                for (int j = 0; j < 4; j++) acc[i][j] += a[i] * b[j];
        }
        __syncthreads();
    }
    float4 bv = *(const float4*)(bias + n0 + tx * 4);
#pragma unroll
    for (int i = 0; i < 8; i++) {
        float4 o;
        o.x = acc[i][0] + bv.x; o.y = acc[i][1] + bv.y;
        o.z = acc[i][2] + bv.z; o.w = acc[i][3] + bv.w;
        *(float4*)(&g_xproj[blockIdx.z][m0 + ty * 8 + i][n0 + tx * 4]) = o;
    }
}

// ---------------- bidirectional LSTM: 2 dirs x 32 persistent CTAs ----------
// CTA (dir, bb) owns h-indices [16*bb, 16*bb+16): 64 gate rows x 512 cols,
// weights register-resident. h exchanged each step through L2 + flags.
// grid=64 < #SMs => all CTAs co-resident in wave 1 => spin-wait is safe.
__global__ void __launch_bounds__(512, 1)
lstm_kernel(const float* __restrict__ w_hh_f, const float* __restrict__ w_hh_b) {
    int cta = blockIdx.x;
    int dir = cta >> 5;
    int bb  = cta & 31;
    const float* Whh = dir ? w_hh_b : w_hh_f;
    int tid = threadIdx.x;
    int r = tid >> 3;            // 0..63 : row within CTA's 64 gate rows
    int s = tid & 7;             // 0..7  : 64-col segment
    int gate = r >> 4;           // 0..3  (i,f,g,o)
    int kloc = r & 15;
    int grow = gate * HH + bb * 16 + kloc;   // global gate row 0..2047

    // register-resident weights: 64 floats
    float w[64];
    {
        const float4* wp = (const float4*)(Whh + (size_t)grow * HH + s * 64);
#pragma unroll
        for (int i = 0; i < 16; i++) {
            float4 v = wp[i];
            w[4 * i + 0] = v.x; w[4 * i + 1] = v.y;
            w[4 * i + 2] = v.z; w[4 * i + 3] = v.w;
        }
    }

    __shared__ float sh[8 * 68];   // padded h stage (pad 4 per 64-seg: no bank conflicts)
    __shared__ float sg[64];       // gate preactivations
    float c_state = 0.f;           // valid for tid<16

    volatile int* myflag = &g_flags[dir * 32 + bb];

    for (int step = 0; step < SEQ; step++) {
        int tcur = dir ? (SEQ - 1 - step) : step;
        float xv = __ldg(&g_xproj[dir][tcur][grow]);   // prefetch early

        if (step == 0) {
            for (int i = tid; i < 8 * 68; i += 512) sh[i] = 0.f;
            __syncthreads();
        } else {
            int tprev = dir ? (tcur + 1) : (tcur - 1);
            if (tid < 32) {
                volatile int* fp = &g_flags[dir * 32 + tid];
                while (*fp < step) { __nanosleep(20); }
                __threadfence();
            }
            __syncthreads();
            if (tid < 128) {
                float4 hv = __ldcg((const float4*)&g_h[dir][tprev][tid * 4]);
                int base = tid * 4;
                int seg = base >> 6, off = base & 63;
                float* d = &sh[seg * 68 + off];
                d[0] = hv.x; d[1] = hv.y; d[2] = hv.z; d[3] = hv.w;
            }
            __syncthreads();
        }

        // matvec partial: 64 cols per thread
        float acc = 0.f;
        const float* hp = &sh[s * 68];
#pragma unroll
        for (int i = 0; i < 16; i++) {
            float4 hv = *(const float4*)(hp + 4 * i);
            acc += w[4 * i + 0] * hv.x;
            acc += w[4 * i + 1] * hv.y;
            acc += w[4 * i + 2] * hv.z;
            acc += w[4 * i + 3] * hv.w;
        }
        acc += __shfl_xor_sync(0xffffffffu, acc, 1);
        acc += __shfl_xor_sync(0xffffffffu, acc, 2);
        acc += __shfl_xor_sync(0xffffffffu, acc, 4);
        if (s == 0) sg[r] = acc + xv;
        __syncthreads();

        if (tid < 16) {
            float gi = sg[tid];
            float gf = sg[16 + tid];
            float gg = sg[32 + tid];
            float go = sg[48 + tid];
            float i_ = 1.f / (1.f + __expf(-gi));
            float f_ = 1.f / (1.f + __expf(-gf));
            float g_ = tanhf(gg);
            float o_ = 1.f / (1.f + __expf(-go));
            float c = f_ * c_state + i_ * g_;
            c_state = c;
            float h = o_ * tanhf(c);
            g_h[dir][tcur][bb * 16 + tid] = h;
        }
        __syncthreads();
        if (tid == 0) {
            __threadfence();          // release h stores (block-wide via barrier cumulativity)
            *myflag = step + 1;
        }
    }
}

// ---------------- feats = [hf, hb] @ w_tag^T + b_tag ----------------
__global__ void feats_kernel(const float* __restrict__ w_tag,
                             const float* __restrict__ b_tag) {
    int t = blockIdx.x;
    int wg   = threadIdx.x >> 5;   // tag 0..7
    int lane = threadIdx.x & 31;
    const float* hf = g_h[0][t];
    const float* hb = g_h[1][t];
    const float* wr = w_tag + wg * 1024;
    float acc = 0.f;
    for (int j = lane; j < 512; j += 32) acc += hf[j] * wr[j];
    for (int j = lane; j < 512; j += 32) acc += hb[j] * wr[512 + j];
#pragma unroll
    for (int d = 16; d > 0; d >>= 1) acc += __shfl_xor_sync(0xffffffffu, acc, d);
    if (lane == 0) g_feats[t * TAGS + wg] = acc + b_tag[wg];
}

// ---------------- Viterbi forward + backtrack + output ----------------
__global__ void viterbi_kernel(const float* __restrict__ trans,
                               float* __restrict__ out, int out_size) {
    __shared__ unsigned char bp[SEQ][TAGS];   // 32 KB
    int lane = threadIdx.x;

    float trow[8];
#pragma unroll
    for (int p = 0; p < 8; p++) trow[p] = (lane < 8) ? trans[lane * 8 + p] : 0.f;

    float fv = (lane == START_TAG) ? 0.f : NEGV;
    float ftn = (lane < 8) ? g_feats[lane] : 0.f;

    for (int t = 0; t < SEQ; t++) {
        float ft = ftn;
        if (t < SEQ - 1 && lane < 8) ftn = g_feats[(t + 1) * TAGS + lane];
        float best = -3.4e38f;
        int bi = 0;
#pragma unroll
        for (int p = 0; p < 8; p++) {
            float fp = __shfl_sync(0xffffffffu, fv, p);
            float sc = fp + trow[p];
            if (sc > best) { best = sc; bi = p; }   // first-max tiebreak
        }
        fv = best + ft;
        if (lane < 8) bp[t][lane] = (unsigned char)bi;
    }

    float term = (lane < 8) ? (fv + trans[STOP_TAG * 8 + lane]) : -3.4e38f;
    int idx = lane;
#pragma unroll
    for (int d = 4; d > 0; d >>= 1) {
        float ov = __shfl_down_sync(0xffffffffu, term, d);
        int   oi = __shfl_down_sync(0xffffffffu, idx,  d);
        if (ov > term || (ov == term && oi < idx)) { term = ov; idx = oi; }
    }
    if (lane == 0) {
        if (out_size > 0) out[0] = term;
        int cur = idx;
        if (1 + (SEQ - 1) < out_size) out[1 + (SEQ - 1)] = (float)cur;
        for (int t = SEQ - 1; t >= 1; t--) {
            cur = bp[t][cur];
            if (t < out_size) out[t] = (float)cur;   // out[1 + (t-1)]
        }
    }
}

// ---------------- launcher ----------------
extern "C" void kernel_launch(void* const* d_in, const int* in_sizes, int n_in,
                              void* d_out, int out_size) {
    const int*   sentence = (const int*)  d_in[0];
    const float* wembed   = (const float*)d_in[1];
    const float* w_ih_f   = (const float*)d_in[2];
    const float* w_hh_f   = (const float*)d_in[3];
    const float* b_f      = (const float*)d_in[4];
    const float* w_ih_b   = (const float*)d_in[5];
    const float* w_hh_b   = (const float*)d_in[6];
    const float* b_b      = (const float*)d_in[7];
    const float* w_tag    = (const float*)d_in[8];
    const float* b_tag    = (const float*)d_in[9];
    const float* trans    = (const float*)d_in[10];

    init_kernel<<<1, 64>>>();
    embed_kernel<<<SEQ, 128>>>(sentence, wembed);
    dim3 gg(G4 / BN, SEQ / BM, 2);
    gemm_kernel<<<gg, 256>>>(w_ih_f, b_f, w_ih_b, b_b);
    lstm_kernel<<<64, 512>>>(w_hh_f, w_hh_b);
    feats_kernel<<<SEQ, 256>>>(w_tag, b_tag);
    viterbi_kernel<<<1, 32>>>(trans, (float*)d_out, out_size);
}